// round 13
// baseline (speedup 1.0000x reference)
#include <cuda_runtime.h>
#include <cuda_bf16.h>
#include <cstdint>

#define NN 32
#define DD 128
#define SS 128
#define MM 64
#define IJ (MM * MM)
#define BASIS 5
#define NT 128        // ij tile per block for the MMA kernel

// ---------------------------------------------------------------------------
// Scratch (static __device__ — no allocations allowed)
// ---------------------------------------------------------------------------
__device__ float g_mc[NN * DD * MM];   // mean over rows i  -> [n][d][j]
__device__ float g_dg[NN * DD * MM];   // diagonal          -> [n][d][t]
__device__ float g_md[NN * DD];        // mean of diag
__device__ float g_ma[NN * DD];        // mean of all
__device__ float g_c0[DD * SS];        // coeffs[d][s][0]  ([d][s])
__device__ float g_c2[DD * SS];        // coeffs[d][s][2]  ([d][s])
__device__ float g_c3[DD * SS];        // coeffs[d][s][3]  ([d][s])
__device__ float g_c4[DD * SS];        // coeffs[d][s][4]  ([d][s])
// A operand pre-built as m16n8k16 fragments: [wm][k0][mt][lane] -> uint4 (a0..a3)
__device__ __align__(16) uint32_t g_AfHi[2 * 8 * 4 * 32 * 4];   // 32 KB
__device__ __align__(16) uint32_t g_AfLo[2 * 8 * 4 * 32 * 4];   // 32 KB
__device__ float g_V2[NN * SS * MM];   // 0.5*V[n][s][t] + 0.5*(B[n][s]+bias[s])

__device__ __forceinline__ uint32_t smem_to_u32(const void* p) {
    uint32_t a;
    asm("{ .reg .u64 t; cvta.to.shared.u64 t, %1; cvt.u32.u64 %0, t; }" : "=r"(a) : "l"(p));
    return a;
}
__device__ __forceinline__ uint32_t pack_bf16x2(__nv_bfloat16 a, __nv_bfloat16 b) {
    __nv_bfloat162 t = __halves2bfloat162(a, b);   // a -> low half
    return *reinterpret_cast<uint32_t*>(&t);
}

// ---------------------------------------------------------------------------
// Kernel 0: pack coefficient planes + build A fragments (hi/lo bf16 split)
// ---------------------------------------------------------------------------
__global__ void pack_coeffs_kernel(const float* __restrict__ coeffs) {
    int idx = blockIdx.x * blockDim.x + threadIdx.x;
    if (idx < DD * SS) {
        const float* c = coeffs + (size_t)idx * BASIS;
        g_c0[idx] = c[0];
        g_c2[idx] = c[2];
        g_c3[idx] = c[3];
        g_c4[idx] = c[4];
    }
    // A fragments: idx over 2048 = wm(2) * k0(8) * mt(4) * lane(32)
    if (idx < 2048) {
        int lane = idx & 31;
        int mt   = (idx >> 5) & 3;
        int k0   = (idx >> 7) & 7;
        int wm   = idx >> 10;
        int r  = lane >> 2;
        int cq = (lane & 3) * 2;
        int s0 = wm * 64 + mt * 16 + r;   // A row (= s)
        int s1 = s0 + 8;
        int d0 = k0 * 16 + cq;            // A col (= d)
        int d1 = d0 + 8;

        float v[4][2];
        v[0][0] = coeffs[(size_t)(d0 * SS + s0) * BASIS + 1];
        v[0][1] = coeffs[(size_t)((d0 + 1) * SS + s0) * BASIS + 1];
        v[1][0] = coeffs[(size_t)(d0 * SS + s1) * BASIS + 1];
        v[1][1] = coeffs[(size_t)((d0 + 1) * SS + s1) * BASIS + 1];
        v[2][0] = coeffs[(size_t)(d1 * SS + s0) * BASIS + 1];
        v[2][1] = coeffs[(size_t)((d1 + 1) * SS + s0) * BASIS + 1];
        v[3][0] = coeffs[(size_t)(d1 * SS + s1) * BASIS + 1];
        v[3][1] = coeffs[(size_t)((d1 + 1) * SS + s1) * BASIS + 1];

        uint32_t hi[4], lo[4];
#pragma unroll
        for (int q = 0; q < 4; q++) {
            __nv_bfloat16 h0 = __float2bfloat16(v[q][0]);
            __nv_bfloat16 h1 = __float2bfloat16(v[q][1]);
            __nv_bfloat16 l0 = __float2bfloat16(v[q][0] - __bfloat162float(h0));
            __nv_bfloat16 l1 = __float2bfloat16(v[q][1] - __bfloat162float(h1));
            hi[q] = pack_bf16x2(h0, h1);
            lo[q] = pack_bf16x2(l0, l1);
        }
        ((uint4*)g_AfHi)[idx] = make_uint4(hi[0], hi[1], hi[2], hi[3]);
        ((uint4*)g_AfLo)[idx] = make_uint4(lo[0], lo[1], lo[2], lo[3]);
    }
}

// ---------------------------------------------------------------------------
// Kernel 1: per-(n,d) reductions
// ---------------------------------------------------------------------------
__global__ __launch_bounds__(64) void reduce_kernel(const float* __restrict__ X) {
    int nd = blockIdx.x;
    const float* x = X + (size_t)nd * IJ;
    int j = threadIdx.x;

    float s = 0.f;
#pragma unroll 8
    for (int i = 0; i < MM; i++) s += x[i * MM + j];
    float mc = s * (1.0f / MM);
    float dg = x[j * MM + j];

    g_mc[nd * MM + j] = mc;
    g_dg[nd * MM + j] = dg;

    __shared__ float sh1[64], sh2[64];
    sh1[j] = dg;
    sh2[j] = mc;
    __syncthreads();
#pragma unroll
    for (int off = 32; off > 0; off >>= 1) {
        if (j < off) { sh1[j] += sh1[j + off]; sh2[j] += sh2[j + off]; }
        __syncthreads();
    }
    if (j == 0) {
        g_md[nd] = sh1[0] * (1.0f / MM);
        g_ma[nd] = sh2[0] * (1.0f / MM);
    }
}

// ---------------------------------------------------------------------------
// Kernel 2: V2[n,s,t] = 0.5*(sum_d c0*mc + c2*dg) + 0.5*(sum_d c3*md + c4*ma + bias)
// ---------------------------------------------------------------------------
__global__ __launch_bounds__(256) void v_kernel(const float* __restrict__ bias) {
    const int st0 = blockIdx.x * 16;
    const int n   = blockIdx.y;
    const int tid = threadIdx.x;
    const int t   = tid & 63;
    const int sg  = tid >> 6;

    __shared__ float c0s[32][16];
    __shared__ float c2s[32][16];
    __shared__ float c3s[32][16];
    __shared__ float c4s[32][16];

    const float* mc = g_mc + (size_t)n * DD * MM;
    const float* dg = g_dg + (size_t)n * DD * MM;
    const float* md = g_md + (size_t)n * DD;
    const float* ma = g_ma + (size_t)n * DD;

    float acc[4]  = {0.f, 0.f, 0.f, 0.f};
    float accb[4] = {0.f, 0.f, 0.f, 0.f};

    for (int d0 = 0; d0 < DD; d0 += 32) {
        __syncthreads();
        // 4 slabs x (32 rows x 16 s) = 512 float4; 256 threads x 2
#pragma unroll
        for (int it = 0; it < 2; it++) {
            int idx = tid + it * 256;          // 0..511
            int arr = idx >> 7;                // slab 0..3
            int rem = idx & 127;
            int r = rem >> 2, c = (rem & 3) * 4;
            const float* src = (arr == 0 ? g_c0 : arr == 1 ? g_c2 : arr == 2 ? g_c3 : g_c4)
                               + (d0 + r) * SS + st0 + c;
            float* dst = (arr == 0 ? &c0s[0][0] : arr == 1 ? &c2s[0][0]
                         : arr == 2 ? &c3s[0][0] : &c4s[0][0]) + r * 16 + c;
            *(float4*)dst = *(const float4*)src;
        }
        __syncthreads();
#pragma unroll 8
        for (int dd = 0; dd < 32; dd++) {
            float mcv = mc[(d0 + dd) * MM + t];
            float dgv = dg[(d0 + dd) * MM + t];
            float mdv = md[d0 + dd];
            float mav = ma[d0 + dd];
#pragma unroll
            for (int q = 0; q < 4; q++) {
                acc[q]  += c0s[dd][sg * 4 + q] * mcv + c2s[dd][sg * 4 + q] * dgv;
                accb[q] += c3s[dd][sg * 4 + q] * mdv + c4s[dd][sg * 4 + q] * mav;
            }
        }
    }

#pragma unroll
    for (int q = 0; q < 4; q++) {
        int s = st0 + sg * 4 + q;
        g_V2[(size_t)(n * SS + s) * MM + t] = 0.5f * (acc[q] + accb[q] + bias[s]);
    }
}

// ---------------------------------------------------------------------------
// Kernel 3: warp-level HMMA bf16x3 split GEMM + fused epilogue.
//   D[s, ij] = Chi*Xhi + Clo*Xhi + Chi*Xlo   (fp32 accum in registers)
// Block: one (n, 128-ij tile), 256 thr = 8 warps (2 s x 4 ij), warp 64x32.
// A: precomputed fragments via LDG (L1 broadcast). B: smem, ROWB=272 pad.
// smem 68 KB -> 2 blocks/SM.
// ---------------------------------------------------------------------------
#define ROWB 272                      // bytes per smem row (136 bf16)
#define SM_BHI 0
#define SM_BLO 34816
#define SMEM_SZ 69632

__device__ __forceinline__ void ldsm_x2t(uint32_t* r, uint32_t addr) {
    asm volatile("ldmatrix.sync.aligned.m8n8.x2.trans.shared.b16 {%0,%1}, [%2];"
                 : "=r"(r[0]), "=r"(r[1]) : "r"(addr));
}
__device__ __forceinline__ void mma16816(float* d, const uint32_t* a, const uint32_t* b) {
    asm volatile("mma.sync.aligned.m16n8k16.row.col.f32.bf16.bf16.f32 "
                 "{%0,%1,%2,%3}, {%4,%5,%6,%7}, {%8,%9}, {%0,%1,%2,%3};"
                 : "+f"(d[0]), "+f"(d[1]), "+f"(d[2]), "+f"(d[3])
                 : "r"(a[0]), "r"(a[1]), "r"(a[2]), "r"(a[3]), "r"(b[0]), "r"(b[1]));
}

__global__ __launch_bounds__(256, 2) void main_hmma_kernel(const float* __restrict__ X,
                                                           float* __restrict__ out) {
    extern __shared__ char smem[];
    const int tid  = threadIdx.x;
    const int lane = tid & 31;
    const int warp = tid >> 5;
    const int warp_m = warp >> 2;       // 0..1 : s half
    const int warp_n = warp & 3;        // 0..3 : ij quarter
    const int tile = blockIdx.x, n = blockIdx.y;
    const int ij0 = tile * NT;

    // ---- stage B (X tile split hi/lo, [d][128 ij] bf16) ----
    {
        const float* xb = X + (size_t)n * DD * IJ + ij0;
#pragma unroll
        for (int k = 0; k < 32; k++) {
            int e = tid + k * 256;           // 8192 float2s
            int d = e >> 6, cp = e & 63;
            float2 x = *(const float2*)(xb + (size_t)d * IJ + cp * 2);
            __nv_bfloat16 h0 = __float2bfloat16(x.x);
            __nv_bfloat16 h1 = __float2bfloat16(x.y);
            __nv_bfloat16 l0 = __float2bfloat16(x.x - __bfloat162float(h0));
            __nv_bfloat16 l1 = __float2bfloat16(x.y - __bfloat162float(h1));
            *(uint32_t*)(smem + SM_BHI + d * ROWB + cp * 4) = pack_bf16x2(h0, h1);
            *(uint32_t*)(smem + SM_BLO + d * ROWB + cp * 4) = pack_bf16x2(l0, l1);
        }
    }
    __syncthreads();

    // ---- per-lane ldmatrix base addresses for B ----
    const uint32_t sb = smem_to_u32(smem);
    uint32_t bBase[4];
#pragma unroll
    for (int nt = 0; nt < 4; nt++)
        bBase[nt] = sb + SM_BHI + (uint32_t)(lane & 15) * ROWB
                  + (uint32_t)(warp_n * 32 + nt * 8) * 2;

    float acc[4][4][4];
#pragma unroll
    for (int mt = 0; mt < 4; mt++)
#pragma unroll
        for (int nt = 0; nt < 4; nt++)
#pragma unroll
            for (int q = 0; q < 4; q++) acc[mt][nt][q] = 0.f;

    // ---- 3 passes: (Ahi,Bhi), (Alo,Bhi), (Ahi,Blo) ----
#pragma unroll
    for (int pass = 0; pass < 3; pass++) {
        const uint4* afrag = (const uint4*)((pass == 1) ? g_AfLo : g_AfHi)
                           + (size_t)warp_m * 8 * 4 * 32;
        const uint32_t bOff = (pass == 2) ? (uint32_t)(SM_BLO - SM_BHI) : 0u;
#pragma unroll
        for (int k0 = 0; k0 < 8; k0++) {
            uint4 av[4];
            uint32_t bf[4][2];
#pragma unroll
            for (int mt = 0; mt < 4; mt++)
                av[mt] = afrag[(k0 * 4 + mt) * 32 + lane];
#pragma unroll
            for (int nt = 0; nt < 4; nt++)
                ldsm_x2t(bf[nt], bBase[nt] + bOff + k0 * 16 * ROWB);
#pragma unroll
            for (int mt = 0; mt < 4; mt++) {
                uint32_t a4[4] = {av[mt].x, av[mt].y, av[mt].z, av[mt].w};
#pragma unroll
                for (int nt = 0; nt < 4; nt++)
                    mma16816(acc[mt][nt], a4, bf[nt]);
            }
        }
    }

    // ---- fused epilogue: out = acc + V2[i] + V2[j] ----
    const float* Vn = g_V2 + (size_t)n * SS * MM;
    const int i_w = tile * 2 + (warp_n >> 1);      // output row i (fixed per warp)
    const int jb  = (warp_n & 1) * 32;             // j base for this warp

#pragma unroll
    for (int mt = 0; mt < 4; mt++) {
        int s0 = warp_m * 64 + mt * 16 + (lane >> 2);
        int s1 = s0 + 8;
        const float* v0 = Vn + s0 * MM;
        const float* v1 = Vn + s1 * MM;
        float e0 = v0[i_w];
        float e1 = v1[i_w];
        float* o0 = out + (((size_t)(n * SS + s0)) * MM + i_w) * MM;
        float* o1 = out + (((size_t)(n * SS + s1)) * MM + i_w) * MM;
#pragma unroll
        for (int nt = 0; nt < 4; nt++) {
            int j = jb + nt * 8 + 2 * (lane & 3);
            float2 r0, r1;
            r0.x = acc[mt][nt][0] + e0 + v0[j];
            r0.y = acc[mt][nt][1] + e0 + v0[j + 1];
            r1.x = acc[mt][nt][2] + e1 + v1[j];
            r1.y = acc[mt][nt][3] + e1 + v1[j + 1];
            *(float2*)(o0 + j) = r0;
            *(float2*)(o1 + j) = r1;
        }
    }
}

// ---------------------------------------------------------------------------
extern "C" void kernel_launch(void* const* d_in, const int* in_sizes, int n_in,
                              void* d_out, int out_size) {
    const float* X      = (const float*)d_in[0];  // [32,128,64,64]
    const float* coeffs = (const float*)d_in[1];  // [128,128,5]
    const float* bias   = (const float*)d_in[2];  // [1,128,1,1]
    float* out = (float*)d_out;

    cudaFuncSetAttribute(main_hmma_kernel, cudaFuncAttributeMaxDynamicSharedMemorySize, SMEM_SZ);

    pack_coeffs_kernel<<<(DD * SS + 255) / 256, 256>>>(coeffs);
    reduce_kernel<<<NN * DD, 64>>>(X);
    v_kernel<<<dim3(8, NN), 256>>>(bias);
    main_hmma_kernel<<<dim3(IJ / NT, NN), 256, SMEM_SZ>>>(X, out);
}